// round 3
// baseline (speedup 1.0000x reference)
#include <cuda_runtime.h>

#define FW 1920
#define FH 1080
#define FHW (FW*FH)
#define CW 3072
#define CH 2048
#define CHW (CW*CH)

__device__ float g_Hinv[9];

__global__ void invert_H_kernel(const float* __restrict__ Hm) {
    if (threadIdx.x != 0 || blockIdx.x != 0) return;
    float a=Hm[0],b=Hm[1],c=Hm[2],d=Hm[3],e=Hm[4],f=Hm[5],g=Hm[6],h=Hm[7],i=Hm[8];
    float A =  (e*i - f*h);
    float B = -(d*i - f*g);
    float C =  (d*h - e*g);
    float det = a*A + b*B + c*C;
    float id = 1.0f / det;
    g_Hinv[0] = A*id;            g_Hinv[1] = -(b*i - c*h)*id;  g_Hinv[2] = (b*f - c*e)*id;
    g_Hinv[3] = B*id;            g_Hinv[4] =  (a*i - c*g)*id;  g_Hinv[5] = -(a*f - c*d)*id;
    g_Hinv[6] = C*id;            g_Hinv[7] = -(a*h - b*g)*id;  g_Hinv[8] = (a*e - b*d)*id;
}

__global__ __launch_bounds__(256)
void warp_composite_kernel(const float* __restrict__ frame,
                           const float* __restrict__ canvas,
                           float* __restrict__ out)
{
    const int g = blockIdx.x * 256 + threadIdx.x;
    if (g >= CH * (CW/4)) return;
    const int y     = g / (CW/4);
    const int xg    = g - y * (CW/4);
    const int xbase = xg * 4;

    const float h0 = g_Hinv[0], h1 = g_Hinv[1], h2 = g_Hinv[2];
    const float h3 = g_Hinv[3], h4 = g_Hinv[4], h5 = g_Hinv[5];
    const float h6 = g_Hinv[6], h7 = g_Hinv[7], h8 = g_Hinv[8];

    const float fy  = (float)y;
    const float fx0 = (float)xbase;

    // One precise reciprocal per thread; Newton-refine per pixel.
    const float Z0  = h6*fx0 + h7*fy + h8;
    const float iz0 = 1.0f / Z0;

    float R[4], G[4], B[4], A[4];

#pragma unroll
    for (int j = 0; j < 4; j++) {
        const float fx = fx0 + (float)j;
        const float X  = h0*fx + h1*fy + h2;
        const float Y  = h3*fx + h4*fy + h5;
        const float Z  = h6*fx + h7*fy + h8;
        const float iz = iz0 * (2.0f - Z * iz0);   // Newton step from iz0
        const float sx = X * iz;
        const float sy = Y * iz;

        const float xf = floorf(sx), yf = floorf(sy);
        const float wx = sx - xf,    wy = sy - yf;
        const int   ix = (int)xf,    iy = (int)yf;

        const float w00 = (1.0f-wx)*(1.0f-wy);
        const float w01 = wx*(1.0f-wy);
        const float w10 = (1.0f-wx)*wy;
        const float w11 = wx*wy;

        float r = 0.0f, gg = 0.0f, bb = 0.0f, as = 0.0f;

        if (ix >= 0 && ix < FW-1 && iy >= 0 && iy < FH-1) {
            // Fully interior: unguarded loads (frame fits in L2).
            const float* p = frame + iy*FW + ix;
            {
                float f00=__ldg(p), f01=__ldg(p+1), f10=__ldg(p+FW), f11=__ldg(p+FW+1);
                r = w00*f00 + w01*f01 + w10*f10 + w11*f11;
            }
            p += FHW;
            {
                float f00=__ldg(p), f01=__ldg(p+1), f10=__ldg(p+FW), f11=__ldg(p+FW+1);
                gg = w00*f00 + w01*f01 + w10*f10 + w11*f11;
            }
            p += FHW;
            {
                float f00=__ldg(p), f01=__ldg(p+1), f10=__ldg(p+FW), f11=__ldg(p+FW+1);
                bb = w00*f00 + w01*f01 + w10*f10 + w11*f11;
            }
            as = (w00 + w01) + (w10 + w11);   // frame alpha channel is 1.0
        } else if (ix >= -1 && ix < FW && iy >= -1 && iy < FH) {
            // Boundary: clamped loads, mask weights.
            const float m00 = (ix >= 0     && iy >= 0    ) ? 1.0f : 0.0f;
            const float m01 = (ix <  FW-1  && iy >= 0    ) ? 1.0f : 0.0f;
            const float m10 = (ix >= 0     && iy <  FH-1 ) ? 1.0f : 0.0f;
            const float m11 = (ix <  FW-1  && iy <  FH-1 ) ? 1.0f : 0.0f;
            const float W00 = w00*m00, W01 = w01*m01, W10 = w10*m10, W11 = w11*m11;
            as = (W00 + W01) + (W10 + W11);

            const int xc0 = max(ix, 0),     xc1 = min(ix+1, FW-1);
            const int yc0 = max(iy, 0),     yc1 = min(iy+1, FH-1);
            const int i00 = yc0*FW + xc0, i01 = yc0*FW + xc1;
            const int i10 = yc1*FW + xc0, i11 = yc1*FW + xc1;

            const float* p = frame;
            r  = W00*__ldg(p+i00) + W01*__ldg(p+i01) + W10*__ldg(p+i10) + W11*__ldg(p+i11);
            p += FHW;
            gg = W00*__ldg(p+i00) + W01*__ldg(p+i01) + W10*__ldg(p+i10) + W11*__ldg(p+i11);
            p += FHW;
            bb = W00*__ldg(p+i00) + W01*__ldg(p+i01) + W10*__ldg(p+i10) + W11*__ldg(p+i11);
        }
        // else: fully outside -> zeros (a_s = 0)

        R[j] = r; G[j] = gg; B[j] = bb; A[j] = as;
    }

    const int base = y*CW + xbase;
    float o0[4], o1[4], o2[4], o3[4];

    const float asmin = fminf(fminf(A[0], A[1]), fminf(A[2], A[3]));
    if (asmin > 0.99999f) {
        // Fully covered: canvas contribution <= 1e-5, skip canvas loads entirely.
#pragma unroll
        for (int j = 0; j < 4; j++) {
            o0[j] = R[j]*A[j];
            o1[j] = G[j]*A[j];
            o2[j] = B[j]*A[j];
            o3[j] = A[j];
        }
    } else {
        float c0[4], c1[4], c2[4], ca[4];
        *(float4*)c0 = *(const float4*)(canvas + 0*CHW + base);
        *(float4*)c1 = *(const float4*)(canvas + 1*CHW + base);
        *(float4*)c2 = *(const float4*)(canvas + 2*CHW + base);
        *(float4*)ca = *(const float4*)(canvas + 3*CHW + base);
#pragma unroll
        for (int j = 0; j < 4; j++) {
            const float as = A[j];
            const float k  = ca[j] * (1.0f - as);
            o0[j] = R[j]*as + c0[j]*k;
            o1[j] = G[j]*as + c1[j]*k;
            o2[j] = B[j]*as + c2[j]*k;
            o3[j] = as + k;
        }
    }

    *(float4*)(out + 0*CHW + base) = *(const float4*)o0;
    *(float4*)(out + 1*CHW + base) = *(const float4*)o1;
    *(float4*)(out + 2*CHW + base) = *(const float4*)o2;
    *(float4*)(out + 3*CHW + base) = *(const float4*)o3;
}

extern "C" void kernel_launch(void* const* d_in, const int* in_sizes, int n_in,
                              void* d_out, int out_size) {
    const float* frame  = (const float*)d_in[0];
    const float* Hmat   = (const float*)d_in[1];
    const float* canvas = (const float*)d_in[2];
    float*       out    = (float*)d_out;

    invert_H_kernel<<<1, 32>>>(Hmat);

    const int total  = CH * (CW/4);            // 1,572,864 threads
    const int blocks = (total + 255) / 256;    // 6144
    warp_composite_kernel<<<blocks, 256>>>(frame, canvas, out);
}

// round 4
// speedup vs baseline: 1.0135x; 1.0135x over previous
#include <cuda_runtime.h>

#define FW 1920
#define FH 1080
#define FHW (FW*FH)
#define CW 3072
#define CH 2048
#define CHW (CW*CH)

__device__ float g_Hinv[9];

__global__ void invert_H_kernel(const float* __restrict__ Hm) {
    if (threadIdx.x != 0 || blockIdx.x != 0) return;
    float a=Hm[0],b=Hm[1],c=Hm[2],d=Hm[3],e=Hm[4],f=Hm[5],g=Hm[6],h=Hm[7],i=Hm[8];
    float A =  (e*i - f*h);
    float B = -(d*i - f*g);
    float C =  (d*h - e*g);
    float det = a*A + b*B + c*C;
    float id = 1.0f / det;
    g_Hinv[0] = A*id;            g_Hinv[1] = -(b*i - c*h)*id;  g_Hinv[2] = (b*f - c*e)*id;
    g_Hinv[3] = B*id;            g_Hinv[4] =  (a*i - c*g)*id;  g_Hinv[5] = -(a*f - c*d)*id;
    g_Hinv[6] = C*id;            g_Hinv[7] = -(a*h - b*g)*id;  g_Hinv[8] = (a*e - b*d)*id;
}

__global__ __launch_bounds__(256, 6)
void warp_composite_kernel(const float* __restrict__ frame,
                           const float* __restrict__ canvas,
                           float* __restrict__ out)
{
    const int y     = blockIdx.y;
    const int xbase = (blockIdx.x * 256 + threadIdx.x) * 4;

    const float h0 = g_Hinv[0], h1 = g_Hinv[1], h2 = g_Hinv[2];
    const float h3 = g_Hinv[3], h4 = g_Hinv[4], h5 = g_Hinv[5];
    const float h6 = g_Hinv[6], h7 = g_Hinv[7], h8 = g_Hinv[8];

    const float fy  = (float)y;
    const float fx0 = (float)xbase;

    // One precise reciprocal per thread; Newton-refine per pixel.
    const float Z0  = h6*fx0 + h7*fy + h8;
    const float iz0 = 1.0f / Z0;

    float wx[4], wy[4];
    int   ix[4], iy[4];

#pragma unroll
    for (int j = 0; j < 4; j++) {
        const float fx = fx0 + (float)j;
        const float X  = h0*fx + h1*fy + h2;
        const float Y  = h3*fx + h4*fy + h5;
        const float Z  = h6*fx + h7*fy + h8;
        const float iz = iz0 * (2.0f - Z * iz0);   // Newton step
        const float sx = X * iz;
        const float sy = Y * iz;
        const float xf = floorf(sx), yf = floorf(sy);
        wx[j] = sx - xf;  wy[j] = sy - yf;
        ix[j] = (int)xf;  iy[j] = (int)yf;
    }

    const int base = y*CW + xbase;

    // Fast path: the 4 source samples are consecutive in x, same row pair,
    // fully interior. Footprints share a 2x5 texel span -> 10 loads/channel
    // instead of 16, and coverage (a_s ~= 1) is guaranteed -> no canvas reads,
    // stream each channel straight to the output.
    const bool fast =
        (iy[1] == iy[0]) && (iy[2] == iy[0]) && (iy[3] == iy[0]) &&
        (ix[1] == ix[0] + 1) && (ix[2] == ix[0] + 2) && (ix[3] == ix[0] + 3) &&
        (ix[0] >= 0) && (ix[0] <= FW - 5) && (iy[0] >= 0) && (iy[0] <= FH - 2);

    if (fast) {
        float w00[4], w01[4], w10[4], w11[4], A[4];
#pragma unroll
        for (int j = 0; j < 4; j++) {
            w00[j] = (1.0f-wx[j])*(1.0f-wy[j]);
            w01[j] = wx[j]*(1.0f-wy[j]);
            w10[j] = (1.0f-wx[j])*wy[j];
            w11[j] = wx[j]*wy[j];
            A[j]   = (w00[j] + w01[j]) + (w10[j] + w11[j]);   // ~= 1
        }

        const float* p = frame + iy[0]*FW + ix[0];
        float* po = out + base;
#pragma unroll
        for (int c = 0; c < 3; c++) {
            const float t0=__ldg(p+0), t1=__ldg(p+1), t2=__ldg(p+2),
                        t3=__ldg(p+3), t4=__ldg(p+4);
            const float b0=__ldg(p+FW+0), b1=__ldg(p+FW+1), b2=__ldg(p+FW+2),
                        b3=__ldg(p+FW+3), b4=__ldg(p+FW+4);
            float o[4];
            o[0] = (w00[0]*t0 + w01[0]*t1 + w10[0]*b0 + w11[0]*b1) * A[0];
            o[1] = (w00[1]*t1 + w01[1]*t2 + w10[1]*b1 + w11[1]*b2) * A[1];
            o[2] = (w00[2]*t2 + w01[2]*t3 + w10[2]*b2 + w11[2]*b3) * A[2];
            o[3] = (w00[3]*t3 + w01[3]*t4 + w10[3]*b3 + w11[3]*b4) * A[3];
            *(float4*)po = *(const float4*)o;
            p  += FHW;
            po += CHW;
        }
        // Alpha channel: frame alpha is 1.0 everywhere, canvas skipped.
        *(float4*)po = *(const float4*)A;
        return;
    }

    // General path: per-pixel interior / boundary / outside handling.
    float R[4], G[4], B[4], A[4];

#pragma unroll
    for (int j = 0; j < 4; j++) {
        const float w00 = (1.0f-wx[j])*(1.0f-wy[j]);
        const float w01 = wx[j]*(1.0f-wy[j]);
        const float w10 = (1.0f-wx[j])*wy[j];
        const float w11 = wx[j]*wy[j];
        const int ixj = ix[j], iyj = iy[j];

        float r = 0.0f, gg = 0.0f, bb = 0.0f, as = 0.0f;

        if (ixj >= 0 && ixj < FW-1 && iyj >= 0 && iyj < FH-1) {
            const float* p = frame + iyj*FW + ixj;
            {
                float f00=__ldg(p), f01=__ldg(p+1), f10=__ldg(p+FW), f11=__ldg(p+FW+1);
                r = w00*f00 + w01*f01 + w10*f10 + w11*f11;
            }
            p += FHW;
            {
                float f00=__ldg(p), f01=__ldg(p+1), f10=__ldg(p+FW), f11=__ldg(p+FW+1);
                gg = w00*f00 + w01*f01 + w10*f10 + w11*f11;
            }
            p += FHW;
            {
                float f00=__ldg(p), f01=__ldg(p+1), f10=__ldg(p+FW), f11=__ldg(p+FW+1);
                bb = w00*f00 + w01*f01 + w10*f10 + w11*f11;
            }
            as = (w00 + w01) + (w10 + w11);
        } else if (ixj >= -1 && ixj < FW && iyj >= -1 && iyj < FH) {
            const float m00 = (ixj >= 0    && iyj >= 0   ) ? 1.0f : 0.0f;
            const float m01 = (ixj <  FW-1 && iyj >= 0   ) ? 1.0f : 0.0f;
            const float m10 = (ixj >= 0    && iyj <  FH-1) ? 1.0f : 0.0f;
            const float m11 = (ixj <  FW-1 && iyj <  FH-1) ? 1.0f : 0.0f;
            const float W00 = w00*m00, W01 = w01*m01, W10 = w10*m10, W11 = w11*m11;
            as = (W00 + W01) + (W10 + W11);

            const int xc0 = max(ixj, 0),   xc1 = min(ixj+1, FW-1);
            const int yc0 = max(iyj, 0),   yc1 = min(iyj+1, FH-1);
            const int i00 = yc0*FW + xc0, i01 = yc0*FW + xc1;
            const int i10 = yc1*FW + xc0, i11 = yc1*FW + xc1;

            const float* p = frame;
            r  = W00*__ldg(p+i00) + W01*__ldg(p+i01) + W10*__ldg(p+i10) + W11*__ldg(p+i11);
            p += FHW;
            gg = W00*__ldg(p+i00) + W01*__ldg(p+i01) + W10*__ldg(p+i10) + W11*__ldg(p+i11);
            p += FHW;
            bb = W00*__ldg(p+i00) + W01*__ldg(p+i01) + W10*__ldg(p+i10) + W11*__ldg(p+i11);
        }
        // else: fully outside -> zeros

        R[j] = r; G[j] = gg; B[j] = bb; A[j] = as;
    }

    float o0[4], o1[4], o2[4], o3[4];
    const float asmin = fminf(fminf(A[0], A[1]), fminf(A[2], A[3]));

    if (asmin > 0.99999f) {
#pragma unroll
        for (int j = 0; j < 4; j++) {
            o0[j] = R[j]*A[j];
            o1[j] = G[j]*A[j];
            o2[j] = B[j]*A[j];
            o3[j] = A[j];
        }
    } else {
        float c0[4], c1[4], c2[4], ca[4];
        *(float4*)c0 = *(const float4*)(canvas + 0*CHW + base);
        *(float4*)c1 = *(const float4*)(canvas + 1*CHW + base);
        *(float4*)c2 = *(const float4*)(canvas + 2*CHW + base);
        *(float4*)ca = *(const float4*)(canvas + 3*CHW + base);
#pragma unroll
        for (int j = 0; j < 4; j++) {
            const float as = A[j];
            const float k  = ca[j] * (1.0f - as);
            o0[j] = R[j]*as + c0[j]*k;
            o1[j] = G[j]*as + c1[j]*k;
            o2[j] = B[j]*as + c2[j]*k;
            o3[j] = as + k;
        }
    }

    *(float4*)(out + 0*CHW + base) = *(const float4*)o0;
    *(float4*)(out + 1*CHW + base) = *(const float4*)o1;
    *(float4*)(out + 2*CHW + base) = *(const float4*)o2;
    *(float4*)(out + 3*CHW + base) = *(const float4*)o3;
}

extern "C" void kernel_launch(void* const* d_in, const int* in_sizes, int n_in,
                              void* d_out, int out_size) {
    const float* frame  = (const float*)d_in[0];
    const float* Hmat   = (const float*)d_in[1];
    const float* canvas = (const float*)d_in[2];
    float*       out    = (float*)d_out;

    invert_H_kernel<<<1, 32>>>(Hmat);

    dim3 grid(CW / (4 * 256), CH);   // (3, 2048)
    warp_composite_kernel<<<grid, 256>>>(frame, canvas, out);
}

// round 5
// speedup vs baseline: 1.0323x; 1.0185x over previous
#include <cuda_runtime.h>

#define FW 1920
#define FH 1080
#define FHW (FW*FH)
#define CW 3072
#define CH 2048
#define CHW (CW*CH)

__device__ float g_Hinv[9];

__global__ void invert_H_kernel(const float* __restrict__ Hm) {
    if (threadIdx.x != 0 || blockIdx.x != 0) return;
    float a=Hm[0],b=Hm[1],c=Hm[2],d=Hm[3],e=Hm[4],f=Hm[5],g=Hm[6],h=Hm[7],i=Hm[8];
    float A =  (e*i - f*h);
    float B = -(d*i - f*g);
    float C =  (d*h - e*g);
    float det = a*A + b*B + c*C;
    float id = 1.0f / det;
    g_Hinv[0] = A*id;            g_Hinv[1] = -(b*i - c*h)*id;  g_Hinv[2] = (b*f - c*e)*id;
    g_Hinv[3] = B*id;            g_Hinv[4] =  (a*i - c*g)*id;  g_Hinv[5] = -(a*f - c*d)*id;
    g_Hinv[6] = C*id;            g_Hinv[7] = -(a*h - b*g)*id;  g_Hinv[8] = (a*e - b*d)*id;
}

// Vertical blocking: each thread = 1 column x 4 consecutive rows.
// Warp lanes cover 32 consecutive x -> every frame/canvas/out access has
// 4-byte lane stride (fully coalesced, 1-2 lines per wavefront).
__global__ __launch_bounds__(256, 6)
void warp_composite_kernel(const float* __restrict__ frame,
                           const float* __restrict__ canvas,
                           float* __restrict__ out)
{
    const int x  = blockIdx.x * 256 + threadIdx.x;
    const int y0 = blockIdx.y * 4;

    const float h0 = g_Hinv[0], h1 = g_Hinv[1], h2 = g_Hinv[2];
    const float h3 = g_Hinv[3], h4 = g_Hinv[4], h5 = g_Hinv[5];
    const float h6 = g_Hinv[6], h7 = g_Hinv[7], h8 = g_Hinv[8];

    const float fx  = (float)x;
    const float fy0 = (float)y0;

    // One precise reciprocal per thread; Newton-refine per pixel.
    const float Z0  = h6*fx + h7*fy0 + h8;
    const float iz0 = 1.0f / Z0;

    float wx[4], wy[4];
    int   ix[4], iy[4];

#pragma unroll
    for (int j = 0; j < 4; j++) {
        const float fy = fy0 + (float)j;
        const float X  = h0*fx + h1*fy + h2;
        const float Y  = h3*fx + h4*fy + h5;
        const float Z  = h6*fx + h7*fy + h8;
        const float iz = iz0 * (2.0f - Z * iz0);   // Newton step
        const float sx = X * iz;
        const float sy = Y * iz;
        const float xf = floorf(sx), yf = floorf(sy);
        wx[j] = sx - xf;  wy[j] = sy - yf;
        ix[j] = (int)xf;  iy[j] = (int)yf;
    }

    const int obase = y0*CW + x;

    float w00[4], w01[4], w10[4], w11[4], A[4];
#pragma unroll
    for (int j = 0; j < 4; j++) {
        w00[j] = (1.0f-wx[j])*(1.0f-wy[j]);
        w01[j] = wx[j]*(1.0f-wy[j]);
        w10[j] = (1.0f-wx[j])*wy[j];
        w11[j] = wx[j]*wy[j];
        A[j]   = (w00[j] + w01[j]) + (w10[j] + w11[j]);
    }

    // Fast path: 4 vertical samples share one column pair and 5 consecutive
    // rows, fully interior. 10 loads/channel, all coalesced across the warp.
    // Coverage is total (a_s ~= 1) -> skip canvas entirely.
    const bool fast =
        (ix[1] == ix[0]) && (ix[2] == ix[0]) && (ix[3] == ix[0]) &&
        (iy[1] == iy[0] + 1) && (iy[2] == iy[0] + 2) && (iy[3] == iy[0] + 3) &&
        (ix[0] >= 0) && (ix[0] <= FW - 2) && (iy[0] >= 0) && (iy[0] <= FH - 5);

    if (fast) {
        const float* p = frame + iy[0]*FW + ix[0];
#pragma unroll
        for (int c = 0; c < 3; c++) {
            float L[5], Rr[5];
#pragma unroll
            for (int r = 0; r < 5; r++) {
                L[r]  = __ldg(p + r*FW);
                Rr[r] = __ldg(p + r*FW + 1);
            }
#pragma unroll
            for (int j = 0; j < 4; j++) {
                const float o = (w00[j]*L[j] + w01[j]*Rr[j]
                               + w10[j]*L[j+1] + w11[j]*Rr[j+1]) * A[j];
                out[c*CHW + obase + j*CW] = o;
            }
            p += FHW;
        }
#pragma unroll
        for (int j = 0; j < 4; j++)
            out[3*CHW + obase + j*CW] = A[j];
        return;
    }

    // General path: per-sample interior / boundary / outside handling.
    float R[4], G[4], B[4];

#pragma unroll
    for (int j = 0; j < 4; j++) {
        const int ixj = ix[j], iyj = iy[j];
        float r = 0.0f, gg = 0.0f, bb = 0.0f;

        if (ixj >= 0 && ixj < FW-1 && iyj >= 0 && iyj < FH-1) {
            const float* p = frame + iyj*FW + ixj;
            {
                float f00=__ldg(p), f01=__ldg(p+1), f10=__ldg(p+FW), f11=__ldg(p+FW+1);
                r = w00[j]*f00 + w01[j]*f01 + w10[j]*f10 + w11[j]*f11;
            }
            p += FHW;
            {
                float f00=__ldg(p), f01=__ldg(p+1), f10=__ldg(p+FW), f11=__ldg(p+FW+1);
                gg = w00[j]*f00 + w01[j]*f01 + w10[j]*f10 + w11[j]*f11;
            }
            p += FHW;
            {
                float f00=__ldg(p), f01=__ldg(p+1), f10=__ldg(p+FW), f11=__ldg(p+FW+1);
                bb = w00[j]*f00 + w01[j]*f01 + w10[j]*f10 + w11[j]*f11;
            }
            // A[j] already = sum of weights ~= 1
        } else if (ixj >= -1 && ixj < FW && iyj >= -1 && iyj < FH) {
            const float m00 = (ixj >= 0    && iyj >= 0   ) ? 1.0f : 0.0f;
            const float m01 = (ixj <  FW-1 && iyj >= 0   ) ? 1.0f : 0.0f;
            const float m10 = (ixj >= 0    && iyj <  FH-1) ? 1.0f : 0.0f;
            const float m11 = (ixj <  FW-1 && iyj <  FH-1) ? 1.0f : 0.0f;
            const float W00 = w00[j]*m00, W01 = w01[j]*m01;
            const float W10 = w10[j]*m10, W11 = w11[j]*m11;
            A[j] = (W00 + W01) + (W10 + W11);

            const int xc0 = max(ixj, 0),   xc1 = min(ixj+1, FW-1);
            const int yc0 = max(iyj, 0),   yc1 = min(iyj+1, FH-1);
            const int i00 = yc0*FW + xc0, i01 = yc0*FW + xc1;
            const int i10 = yc1*FW + xc0, i11 = yc1*FW + xc1;

            const float* p = frame;
            r  = W00*__ldg(p+i00) + W01*__ldg(p+i01) + W10*__ldg(p+i10) + W11*__ldg(p+i11);
            p += FHW;
            gg = W00*__ldg(p+i00) + W01*__ldg(p+i01) + W10*__ldg(p+i10) + W11*__ldg(p+i11);
            p += FHW;
            bb = W00*__ldg(p+i00) + W01*__ldg(p+i01) + W10*__ldg(p+i10) + W11*__ldg(p+i11);
        } else {
            A[j] = 0.0f;   // fully outside
        }

        R[j] = r; G[j] = gg; B[j] = bb;
    }

    const float asmin = fminf(fminf(A[0], A[1]), fminf(A[2], A[3]));

    if (asmin > 0.99999f) {
#pragma unroll
        for (int j = 0; j < 4; j++) {
            out[0*CHW + obase + j*CW] = R[j]*A[j];
            out[1*CHW + obase + j*CW] = G[j]*A[j];
            out[2*CHW + obase + j*CW] = B[j]*A[j];
            out[3*CHW + obase + j*CW] = A[j];
        }
    } else {
#pragma unroll
        for (int j = 0; j < 4; j++) {
            const float as = A[j];
            const float ca = canvas[3*CHW + obase + j*CW];
            const float k  = ca * (1.0f - as);
            out[0*CHW + obase + j*CW] = R[j]*as + canvas[0*CHW + obase + j*CW]*k;
            out[1*CHW + obase + j*CW] = G[j]*as + canvas[1*CHW + obase + j*CW]*k;
            out[2*CHW + obase + j*CW] = B[j]*as + canvas[2*CHW + obase + j*CW]*k;
            out[3*CHW + obase + j*CW] = as + k;
        }
    }
}

extern "C" void kernel_launch(void* const* d_in, const int* in_sizes, int n_in,
                              void* d_out, int out_size) {
    const float* frame  = (const float*)d_in[0];
    const float* Hmat   = (const float*)d_in[1];
    const float* canvas = (const float*)d_in[2];
    float*       out    = (float*)d_out;

    invert_H_kernel<<<1, 32>>>(Hmat);

    dim3 grid(CW / 256, CH / 4);   // (12, 512)
    warp_composite_kernel<<<grid, 256>>>(frame, canvas, out);
}